// round 14
// baseline (speedup 1.0000x reference)
#include <cuda_runtime.h>
#include <cstdint>

// Embedding gather, single-kernel filter-and-gather.
// weight: [1'000'000, 128] f32 (512 MB), index: [2'097'152] i32, out: 1 GB.
//
// NB=64 L2 slices of the table (8 MB each). grid = 64 buckets x 512 blocks;
// blocks are bucket-contiguous so resident blocks share one slice in L2 and
// repeat rows (~57% of draws) hit in L2. Smaller slices (vs 16 MB in R13)
// leave >100 MB of L2 for the streaming writes + index, targeting the last
// ~45 MB of repeat-miss DRAM traffic.
//
// Each block scans its 4096-entry index slice (8 MB index is L2-resident;
// 64x re-read = 512 MB of L2 reads, no DRAM), filters for its bucket
// (~64 matches) with ballot-aggregated compaction, then gathers rows with
// the half-warp 256-bit ld/st pattern.

static constexpr int NB       = 64;
static constexpr int BSHIFT   = 14;               // 2^14 rows per bucket (64*16K >= 1M)
static constexpr int BPB_LOG2 = 9;                // 512 blocks per bucket
static constexpr int BPB      = 1 << BPB_LOG2;
static constexpr int IPB      = 4096;             // index slice per block
static constexpr int C        = 16;               // 32 B chunks per 512 B row
static constexpr int LCAP     = 256;              // shared list capacity (mean 64)

__device__ __forceinline__ ulonglong4 ldg256_evict_last(const ulonglong4* p) {
    ulonglong4 v;
    asm volatile("ld.global.nc.L2::evict_last.v4.u64 {%0,%1,%2,%3}, [%4];"
                 : "=l"(v.x), "=l"(v.y), "=l"(v.z), "=l"(v.w)
                 : "l"(p));
    return v;
}

__device__ __forceinline__ void stg256_cs(ulonglong4* p, const ulonglong4& v) {
    asm volatile("st.global.cs.v4.u64 [%0], {%1,%2,%3,%4};"
                 :: "l"(p), "l"(v.x), "l"(v.y), "l"(v.z), "l"(v.w)
                 : "memory");
}

// Statistically unreachable (cap 256 vs mean 64, sigma ~8); kept correct but
// outside the hot path's register budget.
__device__ __noinline__ void overflow_copy_row(
    const ulonglong4* __restrict__ weight,
    ulonglong4*       __restrict__ out,
    int idx, long long pos)
{
    const ulonglong4* src = &weight[(size_t)idx * C];
    ulonglong4*       dst = &out[pos * C];
#pragma unroll
    for (int c = 0; c < C; c++)
        stg256_cs(&dst[c], ldg256_evict_last(&src[c]));
}

__global__ __launch_bounds__(256, 7) void gather_kernel(
    const ulonglong4* __restrict__ weight,
    const int4*       __restrict__ index4,
    ulonglong4*       __restrict__ out,
    int n_index)
{
    __shared__ int2 list[LCAP];
    __shared__ int  count;

    const int bucket = blockIdx.x >> BPB_LOG2;
    const int lbid   = blockIdx.x & (BPB - 1);
    const int tid    = threadIdx.x;
    const int lane   = tid & 31;
    const unsigned lt_mask = (1u << lane) - 1;

    if (tid == 0) count = 0;
    __syncthreads();

    // ---- Filter phase: scan this block's 4096-index slice (L2-resident). ----
    // n_index == BPB * IPB exactly (2,097,152 = 512 * 4096), so every thread
    // is active and full-mask warp collectives are safe. 16 indices/thread
    // via four int4 loads.
    const long long tpos = (long long)lbid * IPB + tid * 16;
    {
        int idx[16];
#pragma unroll
        for (int q = 0; q < 4; q++) {
            int4 a = __ldg(&index4[tpos / 4 + q]);
            idx[q * 4 + 0] = a.x; idx[q * 4 + 1] = a.y;
            idx[q * 4 + 2] = a.z; idx[q * 4 + 3] = a.w;
        }
#pragma unroll
        for (int i = 0; i < 16; i++) {
            const bool m = (idx[i] >> BSHIFT) == bucket;
            const unsigned mask = __ballot_sync(0xffffffffu, m);
            if (mask) {
                int base = 0;
                if (lane == 0) base = atomicAdd(&count, __popc(mask));
                base = __shfl_sync(0xffffffffu, base, 0);
                if (m) {
                    const int slot = base + __popc(mask & lt_mask);
                    if (slot < LCAP)
                        list[slot] = make_int2((int)(tpos + i), idx[i]);
                    else
                        overflow_copy_row(weight, out, idx[i], tpos + i);
                }
            }
        }
    }
    __syncthreads();

    int cnt = count;
    if (cnt > LCAP) cnt = LCAP;

    // ---- Gather phase: half-warp / 256-bit pattern, 2 pairs per pass. ----
    // Warp handles 4 entries as 2 (even,odd) pairs; a half-warp (16 lanes x
    // 32 B) moves one 512 B row. 8 warps x 4 entries = 32 per pass.
    const int sub  = lane >> 4;                   // 0: even entry, 1: odd entry
    const int l16  = lane & 15;
    const int warp = tid >> 5;

    for (int base = warp * 4; base < cnt; base += 8 * 4) {
        int2 ent[2];
#pragma unroll
        for (int p = 0; p < 2; p++) {
            int e = base + 2 * p + sub;
            ent[p] = (e < cnt) ? list[e] : make_int2(0, 0);
        }

        ulonglong4 v[2];
#pragma unroll
        for (int p = 0; p < 2; p++)
            v[p] = ldg256_evict_last(&weight[(size_t)ent[p].y * C + l16]);

#pragma unroll
        for (int p = 0; p < 2; p++) {
            int e = base + 2 * p + sub;
            if (e < cnt)
                stg256_cs(&out[(size_t)ent[p].x * C + l16], v[p]);
        }
    }
}

extern "C" void kernel_launch(void* const* d_in, const int* in_sizes, int n_in,
                              void* d_out, int out_size)
{
    const ulonglong4* weight = (const ulonglong4*)d_in[0];
    const int4*       index4 = (const int4*)d_in[1];
    ulonglong4*       out    = (ulonglong4*)d_out;

    const int n_index = in_sizes[1];              // 2,097,152 = 512 * 4096

    // One launch: 64 buckets x 512 blocks = 32768 blocks.
    gather_kernel<<<NB << BPB_LOG2, 256>>>(weight, index4, out, n_index);
}

// round 15
// speedup vs baseline: 1.2735x; 1.2735x over previous
#include <cuda_runtime.h>
#include <cstdint>

// Embedding gather, single-kernel filter-and-gather. (Converged best: R12.)
// weight: [1'000'000, 128] f32 (512 MB), index: [2'097'152] i32, out: 1 GB.
//
// NB=32 L2 slices of the table (16 MB each). grid = 32 buckets x 1024 blocks;
// blocks are bucket-contiguous so resident blocks share one slice in L2 and
// repeat rows (~57% of draws) hit in L2 (DRAM reads ~450 MB, not 1045 MB).
//
// No scatter/bins: the 8 MB index is L2-resident; each block re-reads its
// 2048-entry index slice, filters for its bucket (~64 matches), compacts
// (pos, idx) pairs into shared memory, then gathers with half-warp 256-bit
// ld/st (a half-warp moves one 512 B row, 2 row-pairs in flight per warp).
//
// Measured: 241.8 us, DRAM 81.5% (6.46 TB/s), traffic ~1.55 GB vs 1.51 GB
// floor. R13 (ballot compaction) and R14 (NB=64) did not improve on this.

static constexpr int NB       = 32;
static constexpr int BSHIFT   = 15;               // 2^15 rows per bucket
static constexpr int BPB_LOG2 = 10;               // 1024 blocks per bucket
static constexpr int BPB      = 1 << BPB_LOG2;
static constexpr int IPB      = 2048;             // index slice per block
static constexpr int C        = 16;               // 32 B chunks per 512 B row
static constexpr int LCAP     = 256;              // shared list capacity

__device__ __forceinline__ ulonglong4 ldg256_evict_last(const ulonglong4* p) {
    ulonglong4 v;
    asm volatile("ld.global.nc.L2::evict_last.v4.u64 {%0,%1,%2,%3}, [%4];"
                 : "=l"(v.x), "=l"(v.y), "=l"(v.z), "=l"(v.w)
                 : "l"(p));
    return v;
}

__device__ __forceinline__ void stg256_cs(ulonglong4* p, const ulonglong4& v) {
    asm volatile("st.global.cs.v4.u64 [%0], {%1,%2,%3,%4};"
                 :: "l"(p), "l"(v.x), "l"(v.y), "l"(v.z), "l"(v.w)
                 : "memory");
}

// Statistically unreachable (list cap 256 vs mean 64); kept correct but out
// of the hot path's register budget.
__device__ __noinline__ void overflow_copy_row(
    const ulonglong4* __restrict__ weight,
    ulonglong4*       __restrict__ out,
    int idx, long long pos)
{
    const ulonglong4* src = &weight[(size_t)idx * C];
    ulonglong4*       dst = &out[pos * C];
#pragma unroll
    for (int c = 0; c < C; c++)
        stg256_cs(&dst[c], ldg256_evict_last(&src[c]));
}

__global__ __launch_bounds__(256) void gather_kernel(
    const ulonglong4* __restrict__ weight,
    const int4*       __restrict__ index4,
    ulonglong4*       __restrict__ out,
    int n_index)
{
    __shared__ int2 list[LCAP];
    __shared__ int  count;

    const int bucket = blockIdx.x >> BPB_LOG2;
    const int lbid   = blockIdx.x & (BPB - 1);
    const int tid    = threadIdx.x;

    if (tid == 0) count = 0;
    __syncthreads();

    // ---- Filter phase: scan this block's 2048-index slice (L2-resident). ----
    const long long tpos = (long long)lbid * IPB + tid * 8;
    if (tpos < n_index) {
        int4 a = __ldg(&index4[tpos / 4]);
        int4 b = __ldg(&index4[tpos / 4 + 1]);
        int idx[8] = {a.x, a.y, a.z, a.w, b.x, b.y, b.z, b.w};
#pragma unroll
        for (int i = 0; i < 8; i++) {
            if ((idx[i] >> BSHIFT) == bucket) {
                int slot = atomicAdd(&count, 1);
                if (slot < LCAP)
                    list[slot] = make_int2((int)(tpos + i), idx[i]);
                else
                    overflow_copy_row(weight, out, idx[i], tpos + i);
            }
        }
    }
    __syncthreads();

    int cnt = count;
    if (cnt > LCAP) cnt = LCAP;

    // ---- Gather phase: half-warp / 256-bit pattern, 2 pairs per pass. ----
    // Warp handles 4 entries as 2 (even,odd) pairs; a half-warp (16 lanes x
    // 32 B) moves one 512 B row. 8 warps x 4 entries = 32 per pass.
    const int lane = tid & 31;
    const int sub  = lane >> 4;                   // 0: even entry, 1: odd entry
    const int l16  = lane & 15;
    const int warp = tid >> 5;

    for (int base = warp * 4; base < cnt; base += 8 * 4) {
        int2 ent[2];
#pragma unroll
        for (int p = 0; p < 2; p++) {
            int e = base + 2 * p + sub;
            ent[p] = (e < cnt) ? list[e] : make_int2(0, 0);
        }

        ulonglong4 v[2];
#pragma unroll
        for (int p = 0; p < 2; p++)
            v[p] = ldg256_evict_last(&weight[(size_t)ent[p].y * C + l16]);

#pragma unroll
        for (int p = 0; p < 2; p++) {
            int e = base + 2 * p + sub;
            if (e < cnt)
                stg256_cs(&out[(size_t)ent[p].x * C + l16], v[p]);
        }
    }
}

extern "C" void kernel_launch(void* const* d_in, const int* in_sizes, int n_in,
                              void* d_out, int out_size)
{
    const ulonglong4* weight = (const ulonglong4*)d_in[0];
    const int4*       index4 = (const int4*)d_in[1];
    ulonglong4*       out    = (ulonglong4*)d_out;

    const int n_index = in_sizes[1];              // 2,097,152 = 1024 * 2048

    gather_kernel<<<NB << BPB_LOG2, 256>>>(weight, index4, out, n_index);
}